// round 2
// baseline (speedup 1.0000x reference)
#include <cuda_runtime.h>
#include <cstdint>

#define VOCAB 100000
#define EMBED 128
#define ROWS  12800   // 64*200
#define K_ITEMS 50

// 51.2 MB scratch for the transposed weight matrix WT[V][E].
__device__ float g_WT[(size_t)VOCAB * EMBED];

// ---------------------------------------------------------------------------
// Kernel A: transpose W [E=128, V=100000] -> WT [V, E]
// V = 100000 = 32 * 3125 exactly, E = 128 = 32 * 4 exactly -> no bounds checks.
// ---------------------------------------------------------------------------
__global__ void transpose_W(const float* __restrict__ W) {
    __shared__ float tile[32][33];
    const int vt = blockIdx.x * 32;   // 3125 blocks
    const int et = blockIdx.y * 32;   // 4 blocks
    const int tx = threadIdx.x;       // 0..31
    const int ty = threadIdx.y;       // 0..7

    #pragma unroll
    for (int i = 0; i < 32; i += 8) {
        // coalesced read along V
        tile[ty + i][tx] = W[(size_t)(et + ty + i) * VOCAB + (vt + tx)];
    }
    __syncthreads();
    #pragma unroll
    for (int i = 0; i < 32; i += 8) {
        // coalesced write along E
        g_WT[(size_t)(vt + ty + i) * EMBED + (et + tx)] = tile[tx][ty + i];
    }
}

// ---------------------------------------------------------------------------
// Kernel B: embedding-bag gather.
// One warp per output row (b,s). Each lane handles 4 of the 128 embed dims
// as a float4. Ids staged in shared memory per block (8 rows/block).
// NOTE: ids buffer is int32 (JAX downcasts int64 -> int32 without x64 mode).
// ---------------------------------------------------------------------------
#define ROWS_PER_BLOCK 8
#define THREADS_B (ROWS_PER_BLOCK * 32)

__global__ __launch_bounds__(THREADS_B) void gather_rows(
    const int* __restrict__ ids,         // [ROWS, 50] int32
    const float* __restrict__ bias,      // [128]
    float* __restrict__ out)             // [ROWS, 128]
{
    __shared__ int s_ids[ROWS_PER_BLOCK][K_ITEMS];

    const int tid  = threadIdx.x;
    const int lane = tid & 31;
    const int wrow = tid >> 5;                         // 0..7  (row within block)
    const int row0 = blockIdx.x * ROWS_PER_BLOCK;

    // Cooperative, coalesced load of this block's 8*50 = 400 ids.
    const int* gids = ids + (size_t)row0 * K_ITEMS;
    #pragma unroll
    for (int i = tid; i < ROWS_PER_BLOCK * K_ITEMS; i += THREADS_B) {
        s_ids[i / K_ITEMS][i % K_ITEMS] = gids[i];
    }
    __syncthreads();

    const int row = row0 + wrow;

    float4 acc = make_float4(0.f, 0.f, 0.f, 0.f);

    #pragma unroll 10
    for (int k = 0; k < K_ITEMS; k++) {
        const int v = s_ids[wrow][k];
        if (v != 0) {
            const float4 g = __ldg((const float4*)(g_WT + (size_t)v * EMBED) + lane);
            acc.x += g.x; acc.y += g.y; acc.z += g.z; acc.w += g.w;
        }
    }

    const float4 bv = __ldg((const float4*)bias + lane);
    acc.x += bv.x; acc.y += bv.y; acc.z += bv.z; acc.w += bv.w;

    ((float4*)(out + (size_t)row * EMBED))[lane] = acc;
}

// ---------------------------------------------------------------------------
// Entry point. Inputs (metadata order): content_input int32, W f32, b f32.
// ---------------------------------------------------------------------------
extern "C" void kernel_launch(void* const* d_in, const int* in_sizes, int n_in,
                              void* d_out, int out_size) {
    const int*   ids = (const int*)d_in[0];
    const float* W   = (const float*)d_in[1];
    const float* b   = (const float*)d_in[2];
    float*       out = (float*)d_out;

    dim3 tgrid(VOCAB / 32, EMBED / 32);
    dim3 tblk(32, 8);
    transpose_W<<<tgrid, tblk>>>(W);

    gather_rows<<<ROWS / ROWS_PER_BLOCK, THREADS_B>>>(ids, b, out);
}

// round 3
// speedup vs baseline: 1.0406x; 1.0406x over previous
#include <cuda_runtime.h>
#include <cstdint>

#define VOCAB 100000
#define EMBED 128
#define ROWS  12800   // 64*200
#define K_ITEMS 50

// 51.2 MB scratch for the transposed weight matrix WT[V][E].
__device__ float g_WT[(size_t)VOCAB * EMBED];

// ---------------------------------------------------------------------------
// Kernel A: transpose W [E=128, V=100000] -> WT [V, E], fully vectorized.
// Tile: 32 E x 160 V per block. float4 global loads AND stores.
// Smem uses a non-linear bank map idx(v,e) = v*32 + ((e + v + (v>>2)) & 31),
// which is conflict-free for BOTH the v-stride-4 scalar stores (Δbank = 5,
// coprime with 32) and the e-stride-4 scalar loads (d + 4*e4 + j distinct).
// V = 100000 -> 25000 float4 per e-row; 25000 / 40 = 625 exact. E/32 = 4.
// ---------------------------------------------------------------------------
#define VT 160        // v per tile
#define F4T 40        // float4 per e-row per tile
#define ET 32         // e per tile

__device__ __forceinline__ int swz(int v, int e) {
    return v * 32 + ((e + v + (v >> 2)) & 31);
}

__global__ __launch_bounds__(256) void transpose_W(const float4* __restrict__ W4) {
    __shared__ float s[VT * 32];   // 20 KB

    const int tid = threadIdx.x;
    const int vt4 = blockIdx.x * F4T;    // float4 offset along V
    const int vt  = blockIdx.x * VT;     // float offset along V
    const int et  = blockIdx.y * ET;     // float offset along E
    const int et4 = blockIdx.y * (ET / 4);

    // ---- Read: 32 e-rows x 40 float4 = 1280 float4, 5 per thread ----
    #pragma unroll
    for (int i = 0; i < 5; i++) {
        const int idx = i * 256 + tid;
        const int e = idx / F4T;          // 0..31
        const int c = idx % F4T;          // 0..39
        const float4 w = W4[(size_t)(et + e) * (VOCAB / 4) + vt4 + c];
        const int v = 4 * c;
        s[swz(v + 0, e)] = w.x;
        s[swz(v + 1, e)] = w.y;
        s[swz(v + 2, e)] = w.z;
        s[swz(v + 3, e)] = w.w;
    }
    __syncthreads();

    // ---- Write: 160 v-rows x 8 float4 = 1280 float4, 5 per thread ----
    float4* WT4 = (float4*)g_WT;
    #pragma unroll
    for (int i = 0; i < 5; i++) {
        const int idx = i * 256 + tid;
        const int v  = idx >> 3;          // 0..159
        const int e4 = idx & 7;           // 0..7
        const int e  = 4 * e4;
        float4 o;
        o.x = s[swz(v, e + 0)];
        o.y = s[swz(v, e + 1)];
        o.z = s[swz(v, e + 2)];
        o.w = s[swz(v, e + 3)];
        WT4[(size_t)(vt + v) * (EMBED / 4) + et4 + e4] = o;
    }
}

// ---------------------------------------------------------------------------
// Kernel B: embedding-bag gather (unchanged — measured at the LTS roofline).
// One warp per output row (b,s). Each lane handles 4 of the 128 embed dims
// as a float4. Ids staged in shared memory per block (8 rows/block).
// ---------------------------------------------------------------------------
#define ROWS_PER_BLOCK 8
#define THREADS_B (ROWS_PER_BLOCK * 32)

__global__ __launch_bounds__(THREADS_B) void gather_rows(
    const int* __restrict__ ids,         // [ROWS, 50] int32
    const float* __restrict__ bias,      // [128]
    float* __restrict__ out)             // [ROWS, 128]
{
    __shared__ int s_ids[ROWS_PER_BLOCK][K_ITEMS];

    const int tid  = threadIdx.x;
    const int lane = tid & 31;
    const int wrow = tid >> 5;
    const int row0 = blockIdx.x * ROWS_PER_BLOCK;

    const int* gids = ids + (size_t)row0 * K_ITEMS;
    #pragma unroll
    for (int i = tid; i < ROWS_PER_BLOCK * K_ITEMS; i += THREADS_B) {
        s_ids[i / K_ITEMS][i % K_ITEMS] = gids[i];
    }
    __syncthreads();

    const int row = row0 + wrow;

    float4 acc = make_float4(0.f, 0.f, 0.f, 0.f);

    #pragma unroll 10
    for (int k = 0; k < K_ITEMS; k++) {
        const int v = s_ids[wrow][k];
        if (v != 0) {
            const float4 g = __ldg((const float4*)(g_WT + (size_t)v * EMBED) + lane);
            acc.x += g.x; acc.y += g.y; acc.z += g.z; acc.w += g.w;
        }
    }

    const float4 bv = __ldg((const float4*)bias + lane);
    acc.x += bv.x; acc.y += bv.y; acc.z += bv.z; acc.w += bv.w;

    ((float4*)(out + (size_t)row * EMBED))[lane] = acc;
}

// ---------------------------------------------------------------------------
// Entry point. Inputs (metadata order): content_input int32, W f32, b f32.
// ---------------------------------------------------------------------------
extern "C" void kernel_launch(void* const* d_in, const int* in_sizes, int n_in,
                              void* d_out, int out_size) {
    const int*   ids = (const int*)d_in[0];
    const float* W   = (const float*)d_in[1];
    const float* b   = (const float*)d_in[2];
    float*       out = (float*)d_out;

    dim3 tgrid(VOCAB / VT, EMBED / ET);   // 625 x 4
    transpose_W<<<tgrid, 256>>>((const float4*)W);

    gather_rows<<<ROWS / ROWS_PER_BLOCK, THREADS_B>>>(ids, b, out);
}

// round 4
// speedup vs baseline: 1.5876x; 1.5257x over previous
#include <cuda_runtime.h>
#include <cuda_fp16.h>
#include <cstdint>

#define VOCAB 100000
#define EMBED 128
#define ROWS  12800   // 64*200
#define K_ITEMS 50

// 25.6 MB scratch: transposed weights WT[V][E] in fp16.
__device__ __half g_WT[(size_t)VOCAB * EMBED];

// ---------------------------------------------------------------------------
// Kernel A: transpose W [E=128, V=100000] (fp32) -> WT [V, E] (fp16).
// Tile: 32 E x 160 V per block. float4 global loads, uint2 (4xhalf) stores.
// Smem bank map idx(v,e) = v*32 + ((e + v + (v>>2)) & 31): conflict-free for
// the v-stride-4 scalar stores (Δbank=5, coprime 32) and e-stride-4 loads.
// ---------------------------------------------------------------------------
#define VT 160        // v per tile
#define F4T 40        // float4 per e-row per tile
#define ET 32         // e per tile

__device__ __forceinline__ int swz(int v, int e) {
    return v * 32 + ((e + v + (v >> 2)) & 31);
}

__global__ __launch_bounds__(256) void transpose_W(const float4* __restrict__ W4) {
    __shared__ float s[VT * 32];   // 20 KB

    const int tid = threadIdx.x;
    const int vt4 = blockIdx.x * F4T;    // float4 offset along V
    const int vt  = blockIdx.x * VT;     // float offset along V
    const int et  = blockIdx.y * ET;     // float offset along E

    // ---- Read: 32 e-rows x 40 float4 = 1280 float4, 5 per thread ----
    #pragma unroll
    for (int i = 0; i < 5; i++) {
        const int idx = i * 256 + tid;
        const int e = idx / F4T;          // 0..31
        const int c = idx % F4T;          // 0..39
        const float4 w = W4[(size_t)(et + e) * (VOCAB / 4) + vt4 + c];
        const int v = 4 * c;
        s[swz(v + 0, e)] = w.x;
        s[swz(v + 1, e)] = w.y;
        s[swz(v + 2, e)] = w.z;
        s[swz(v + 3, e)] = w.w;
    }
    __syncthreads();

    // ---- Write: 160 v-rows x 8 uint2 (4 halves each) = 1280, 5 per thread ----
    uint2* WT_u2 = (uint2*)g_WT;          // 8 B = 4 halves per element
    #pragma unroll
    for (int i = 0; i < 5; i++) {
        const int idx = i * 256 + tid;
        const int v  = idx >> 3;          // 0..159
        const int e4 = idx & 7;           // 0..7  -> halves 4*e4 .. 4*e4+3
        const int e  = 4 * e4;
        __half2 h0 = __floats2half2_rn(s[swz(v, e + 0)], s[swz(v, e + 1)]);
        __half2 h1 = __floats2half2_rn(s[swz(v, e + 2)], s[swz(v, e + 3)]);
        uint2 o;
        o.x = *reinterpret_cast<unsigned int*>(&h0);
        o.y = *reinterpret_cast<unsigned int*>(&h1);
        // WT row = 128 halves = 32 uint2; this thread covers uint2 slot (et>>2)+e4
        WT_u2[(size_t)(vt + v) * (EMBED / 4) + (et >> 2) + e4] = o;
    }
}

// ---------------------------------------------------------------------------
// Kernel B: embedding-bag gather from fp16 WT, fp32 accumulate.
// One warp per output row. Lane owns dims 4*lane..4*lane+3 (one uint2 = 4
// halves per id -> 256 B contiguous per row per id). Ids staged in smem.
// ---------------------------------------------------------------------------
#define ROWS_PER_BLOCK 8
#define THREADS_B (ROWS_PER_BLOCK * 32)

__global__ __launch_bounds__(THREADS_B) void gather_rows(
    const int* __restrict__ ids,         // [ROWS, 50] int32
    const float* __restrict__ bias,      // [128] fp32
    float* __restrict__ out)             // [ROWS, 128] fp32
{
    __shared__ int s_ids[ROWS_PER_BLOCK][K_ITEMS];

    const int tid  = threadIdx.x;
    const int lane = tid & 31;
    const int wrow = tid >> 5;
    const int row0 = blockIdx.x * ROWS_PER_BLOCK;

    const int* gids = ids + (size_t)row0 * K_ITEMS;
    #pragma unroll
    for (int i = tid; i < ROWS_PER_BLOCK * K_ITEMS; i += THREADS_B) {
        s_ids[i / K_ITEMS][i % K_ITEMS] = gids[i];
    }
    __syncthreads();

    const int row = row0 + wrow;

    float4 acc = make_float4(0.f, 0.f, 0.f, 0.f);

    #pragma unroll 10
    for (int k = 0; k < K_ITEMS; k++) {
        const int v = s_ids[wrow][k];
        if (v != 0) {
            const uint2 r = __ldg((const uint2*)(g_WT + (size_t)v * EMBED) + lane);
            const __half2 h0 = *reinterpret_cast<const __half2*>(&r.x);
            const __half2 h1 = *reinterpret_cast<const __half2*>(&r.y);
            const float2 f0 = __half22float2(h0);
            const float2 f1 = __half22float2(h1);
            acc.x += f0.x; acc.y += f0.y; acc.z += f1.x; acc.w += f1.y;
        }
    }

    const float4 bv = __ldg((const float4*)bias + lane);
    acc.x += bv.x; acc.y += bv.y; acc.z += bv.z; acc.w += bv.w;

    ((float4*)(out + (size_t)row * EMBED))[lane] = acc;
}

// ---------------------------------------------------------------------------
// Entry point. Inputs (metadata order): content_input int32, W f32, b f32.
// ---------------------------------------------------------------------------
extern "C" void kernel_launch(void* const* d_in, const int* in_sizes, int n_in,
                              void* d_out, int out_size) {
    const int*   ids = (const int*)d_in[0];
    const float* W   = (const float*)d_in[1];
    const float* b   = (const float*)d_in[2];
    float*       out = (float*)d_out;

    dim3 tgrid(VOCAB / VT, EMBED / ET);   // 625 x 4
    transpose_W<<<tgrid, 256>>>((const float4*)W);

    gather_rows<<<ROWS / ROWS_PER_BLOCK, THREADS_B>>>(ids, b, out);
}

// round 5
// speedup vs baseline: 1.6026x; 1.0094x over previous
#include <cuda_runtime.h>
#include <cuda_fp16.h>
#include <cstdint>

#define VOCAB 100000
#define EMBED 128
#define ROWS  12800   // 64*200
#define K_ITEMS 50

// 25.6 MB scratch: transposed weights WT[V][E] in fp16. Row 0 is zeroed by
// the transpose so the gather needs no id!=0 mask.
__device__ __align__(256) __half g_WT[(size_t)VOCAB * EMBED];

// ---------------------------------------------------------------------------
// Kernel A: transpose W [E=128, V=100000] (fp32) -> WT [V, E] (fp16).
// Tile: 32 E x 160 V per block. float4 global loads, uint2 (4xhalf) stores.
// Smem bank map idx(v,e) = v*32 + ((e + v + (v>>2)) & 31): conflict-free for
// the v-stride-4 scalar stores (Δbank=5, coprime 32) and e-stride-4 loads.
// Row v==0 of WT is written as zeros (multi-hot column 0 is masked out).
// ---------------------------------------------------------------------------
#define VT 160        // v per tile
#define F4T 40        // float4 per e-row per tile
#define ET 32         // e per tile

__device__ __forceinline__ int swz(int v, int e) {
    return v * 32 + ((e + v + (v >> 2)) & 31);
}

__global__ __launch_bounds__(256) void transpose_W(const float4* __restrict__ W4) {
    __shared__ float s[VT * 32];   // 20 KB

    const int tid = threadIdx.x;
    const int vt4 = blockIdx.x * F4T;    // float4 offset along V
    const int vt  = blockIdx.x * VT;     // float offset along V
    const int et  = blockIdx.y * ET;     // float offset along E

    // ---- Read: 32 e-rows x 40 float4 = 1280 float4, 5 per thread ----
    #pragma unroll
    for (int i = 0; i < 5; i++) {
        const int idx = i * 256 + tid;
        const int e = idx / F4T;          // 0..31
        const int c = idx % F4T;          // 0..39
        const float4 w = W4[(size_t)(et + e) * (VOCAB / 4) + vt4 + c];
        const int v = 4 * c;
        s[swz(v + 0, e)] = w.x;
        s[swz(v + 1, e)] = w.y;
        s[swz(v + 2, e)] = w.z;
        s[swz(v + 3, e)] = w.w;
    }
    __syncthreads();

    // ---- Write: 160 v-rows x 8 uint2 (4 halves each) = 1280, 5 per thread ----
    uint2* WT_u2 = (uint2*)g_WT;          // 8 B = 4 halves per element
    #pragma unroll
    for (int i = 0; i < 5; i++) {
        const int idx = i * 256 + tid;
        const int v  = idx >> 3;          // 0..159
        const int e4 = idx & 7;           // 0..7
        const int e  = 4 * e4;
        __half2 h0 = __floats2half2_rn(s[swz(v, e + 0)], s[swz(v, e + 1)]);
        __half2 h1 = __floats2half2_rn(s[swz(v, e + 2)], s[swz(v, e + 3)]);
        uint2 o;
        o.x = *reinterpret_cast<unsigned int*>(&h0);
        o.y = *reinterpret_cast<unsigned int*>(&h1);
        if (vt + v == 0) { o.x = 0u; o.y = 0u; }   // mask column 0
        WT_u2[(size_t)(vt + v) * (EMBED / 4) + (et >> 2) + e4] = o;
    }
}

// ---------------------------------------------------------------------------
// Kernel B: embedding-bag gather from fp16 WT, fp32 accumulate.
// One warp per output row; each HALF-warp fetches one full 256 B WT row via
// LDG.128 (16 lanes x 16 B), so the warp consumes 2 ids per iteration ->
// 25 iterations, branch-free (row 0 of WT is zero). A single shfl_xor(16)
// merges the two half-warp partial sums at the end.
// ---------------------------------------------------------------------------
#define ROWS_PER_BLOCK 8
#define THREADS_B (ROWS_PER_BLOCK * 32)

__global__ __launch_bounds__(THREADS_B) void gather_rows(
    const int* __restrict__ ids,         // [ROWS, 50] int32
    const float* __restrict__ bias,      // [128] fp32
    float* __restrict__ out)             // [ROWS, 128] fp32
{
    __shared__ int s_ids[ROWS_PER_BLOCK][K_ITEMS];

    const int tid  = threadIdx.x;
    const int lane = tid & 31;
    const int wrow = tid >> 5;
    const int row0 = blockIdx.x * ROWS_PER_BLOCK;
    const int sub  = lane & 15;          // lane within half-warp
    const int half = lane >> 4;          // which id of the pair

    const int* gids = ids + (size_t)row0 * K_ITEMS;
    #pragma unroll
    for (int i = tid; i < ROWS_PER_BLOCK * K_ITEMS; i += THREADS_B) {
        s_ids[i / K_ITEMS][i % K_ITEMS] = gids[i];
    }
    __syncthreads();

    float a0 = 0.f, a1 = 0.f, a2 = 0.f, a3 = 0.f;
    float a4 = 0.f, a5 = 0.f, a6 = 0.f, a7 = 0.f;

    #pragma unroll 5
    for (int k = 0; k < K_ITEMS / 2; k++) {
        const int v = s_ids[wrow][2 * k + half];
        const int4 r = __ldg((const int4*)(g_WT + (size_t)v * EMBED) + sub);
        const float2 f0 = __half22float2(*reinterpret_cast<const __half2*>(&r.x));
        const float2 f1 = __half22float2(*reinterpret_cast<const __half2*>(&r.y));
        const float2 f2 = __half22float2(*reinterpret_cast<const __half2*>(&r.z));
        const float2 f3 = __half22float2(*reinterpret_cast<const __half2*>(&r.w));
        a0 += f0.x; a1 += f0.y; a2 += f1.x; a3 += f1.y;
        a4 += f2.x; a5 += f2.y; a6 += f3.x; a7 += f3.y;
    }

    // Merge the two half-warp partial sums (each covered different ids).
    a0 += __shfl_xor_sync(0xffffffffu, a0, 16);
    a1 += __shfl_xor_sync(0xffffffffu, a1, 16);
    a2 += __shfl_xor_sync(0xffffffffu, a2, 16);
    a3 += __shfl_xor_sync(0xffffffffu, a3, 16);
    a4 += __shfl_xor_sync(0xffffffffu, a4, 16);
    a5 += __shfl_xor_sync(0xffffffffu, a5, 16);
    a6 += __shfl_xor_sync(0xffffffffu, a6, 16);
    a7 += __shfl_xor_sync(0xffffffffu, a7, 16);

    // Lane writes float4 slot j = 2*sub + half (dims 8*sub + 4*half ..+3).
    const int j = 2 * sub + half;
    float4 o = (half == 0) ? make_float4(a0, a1, a2, a3)
                           : make_float4(a4, a5, a6, a7);
    const float4 bv = __ldg((const float4*)bias + j);
    o.x += bv.x; o.y += bv.y; o.z += bv.z; o.w += bv.w;
    ((float4*)(out + (size_t)(row0 + wrow) * EMBED))[j] = o;
}

// ---------------------------------------------------------------------------
// Entry point. Inputs (metadata order): content_input int32, W f32, b f32.
// ---------------------------------------------------------------------------
extern "C" void kernel_launch(void* const* d_in, const int* in_sizes, int n_in,
                              void* d_out, int out_size) {
    const int*   ids = (const int*)d_in[0];
    const float* W   = (const float*)d_in[1];
    const float* b   = (const float*)d_in[2];
    float*       out = (float*)d_out;

    dim3 tgrid(VOCAB / VT, EMBED / ET);   // 625 x 4
    transpose_W<<<tgrid, 256>>>((const float4*)W);

    gather_rows<<<ROWS / ROWS_PER_BLOCK, THREADS_B>>>(ids, b, out);
}

// round 6
// speedup vs baseline: 1.6413x; 1.0242x over previous
#include <cuda_runtime.h>
#include <cuda_fp16.h>
#include <cstdint>

#define VOCAB 100000
#define EMBED 128
#define ROWS  12800   // 64*200
#define K_ITEMS 50

// 25.6 MB scratch: transposed weights WT[V][E] in fp16. Row 0 is zeroed by
// the transpose so the gather needs no id!=0 mask.
__device__ __align__(256) __half g_WT[(size_t)VOCAB * EMBED];

// ---------------------------------------------------------------------------
// Kernel A: transpose W [E=128, V=100000] (fp32) -> WT [V, E] (fp16).
// Tile: 32 E x 160 V per block. float4 global loads, uint2 (4xhalf) stores.
// Smem bank map idx(v,e) = v*32 + ((e + v + (v>>2)) & 31): conflict-free for
// the v-stride-4 scalar stores (Δbank=5, coprime 32) and e-stride-4 loads.
// Row v==0 of WT is written as zeros (multi-hot column 0 is masked out).
// ---------------------------------------------------------------------------
#define VT 160        // v per tile
#define F4T 40        // float4 per e-row per tile
#define ET 32         // e per tile

__device__ __forceinline__ int swz(int v, int e) {
    return v * 32 + ((e + v + (v >> 2)) & 31);
}

__global__ __launch_bounds__(256) void transpose_W(const float4* __restrict__ W4) {
    __shared__ float s[VT * 32];   // 20 KB

    const int tid = threadIdx.x;
    const int vt4 = blockIdx.x * F4T;    // float4 offset along V
    const int vt  = blockIdx.x * VT;     // float offset along V
    const int et  = blockIdx.y * ET;     // float offset along E

    #pragma unroll
    for (int i = 0; i < 5; i++) {
        const int idx = i * 256 + tid;
        const int e = idx / F4T;          // 0..31
        const int c = idx % F4T;          // 0..39
        const float4 w = W4[(size_t)(et + e) * (VOCAB / 4) + vt4 + c];
        const int v = 4 * c;
        s[swz(v + 0, e)] = w.x;
        s[swz(v + 1, e)] = w.y;
        s[swz(v + 2, e)] = w.z;
        s[swz(v + 3, e)] = w.w;
    }
    __syncthreads();

    uint2* WT_u2 = (uint2*)g_WT;          // 8 B = 4 halves per element
    #pragma unroll
    for (int i = 0; i < 5; i++) {
        const int idx = i * 256 + tid;
        const int v  = idx >> 3;          // 0..159
        const int e4 = idx & 7;           // 0..7
        const int e  = 4 * e4;
        __half2 h0 = __floats2half2_rn(s[swz(v, e + 0)], s[swz(v, e + 1)]);
        __half2 h1 = __floats2half2_rn(s[swz(v, e + 2)], s[swz(v, e + 3)]);
        uint2 o;
        o.x = *reinterpret_cast<unsigned int*>(&h0);
        o.y = *reinterpret_cast<unsigned int*>(&h1);
        if (vt + v == 0) { o.x = 0u; o.y = 0u; }   // mask column 0
        WT_u2[(size_t)(vt + v) * (EMBED / 4) + (et >> 2) + e4] = o;
    }
}

// ---------------------------------------------------------------------------
// Kernel B: embedding-bag gather from fp16 WT.
// One warp per output row; each HALF-warp fetches one full 256 B WT row via
// LDG.128, so a warp consumes 2 ids/iteration -> 25 iterations split into
// 5 groups of 5. Within a group, accumulation is in fp16 (HADD2, 4/id);
// groups are flushed into fp32 accumulators (error ~5e-4 total, gate 1e-3).
// Branch-free (WT row 0 is zero). shfl_xor(16) merges half-warp partials.
// ---------------------------------------------------------------------------
#define ROWS_PER_BLOCK 4
#define THREADS_B (ROWS_PER_BLOCK * 32)

__global__ __launch_bounds__(THREADS_B) void gather_rows(
    const int* __restrict__ ids,         // [ROWS, 50] int32
    const float* __restrict__ bias,      // [128] fp32
    float* __restrict__ out)             // [ROWS, 128] fp32
{
    __shared__ int s_ids[ROWS_PER_BLOCK][K_ITEMS];

    const int tid  = threadIdx.x;
    const int lane = tid & 31;
    const int wrow = tid >> 5;
    const int row0 = blockIdx.x * ROWS_PER_BLOCK;
    const int sub  = lane & 15;          // lane within half-warp
    const int half = lane >> 4;          // which id of the pair

    const int* gids = ids + (size_t)row0 * K_ITEMS;
    #pragma unroll
    for (int i = tid; i < ROWS_PER_BLOCK * K_ITEMS; i += THREADS_B) {
        s_ids[i / K_ITEMS][i % K_ITEMS] = gids[i];
    }
    __syncthreads();

    float a0 = 0.f, a1 = 0.f, a2 = 0.f, a3 = 0.f;
    float a4 = 0.f, a5 = 0.f, a6 = 0.f, a7 = 0.f;

    #pragma unroll
    for (int g = 0; g < 5; g++) {
        const __half2 z = __float2half2_rn(0.f);
        __half2 h0 = z, h1 = z, h2 = z, h3 = z;

        #pragma unroll
        for (int j = 0; j < 5; j++) {
            const int v = s_ids[wrow][10 * g + 2 * j + half];
            const int4 r = __ldg((const int4*)(g_WT + (size_t)v * EMBED) + sub);
            h0 = __hadd2(h0, *reinterpret_cast<const __half2*>(&r.x));
            h1 = __hadd2(h1, *reinterpret_cast<const __half2*>(&r.y));
            h2 = __hadd2(h2, *reinterpret_cast<const __half2*>(&r.z));
            h3 = __hadd2(h3, *reinterpret_cast<const __half2*>(&r.w));
        }

        const float2 f0 = __half22float2(h0);
        const float2 f1 = __half22float2(h1);
        const float2 f2 = __half22float2(h2);
        const float2 f3 = __half22float2(h3);
        a0 += f0.x; a1 += f0.y; a2 += f1.x; a3 += f1.y;
        a4 += f2.x; a5 += f2.y; a6 += f3.x; a7 += f3.y;
    }

    // Merge the two half-warp partial sums (each covered different ids).
    a0 += __shfl_xor_sync(0xffffffffu, a0, 16);
    a1 += __shfl_xor_sync(0xffffffffu, a1, 16);
    a2 += __shfl_xor_sync(0xffffffffu, a2, 16);
    a3 += __shfl_xor_sync(0xffffffffu, a3, 16);
    a4 += __shfl_xor_sync(0xffffffffu, a4, 16);
    a5 += __shfl_xor_sync(0xffffffffu, a5, 16);
    a6 += __shfl_xor_sync(0xffffffffu, a6, 16);
    a7 += __shfl_xor_sync(0xffffffffu, a7, 16);

    // Lane writes float4 slot j = 2*sub + half (dims 8*sub + 4*half ..+3).
    const int j = 2 * sub + half;
    float4 o = (half == 0) ? make_float4(a0, a1, a2, a3)
                           : make_float4(a4, a5, a6, a7);
    const float4 bv = __ldg((const float4*)bias + j);
    o.x += bv.x; o.y += bv.y; o.z += bv.z; o.w += bv.w;
    ((float4*)(out + (size_t)(row0 + wrow) * EMBED))[j] = o;
}

// ---------------------------------------------------------------------------
// Entry point. Inputs (metadata order): content_input int32, W f32, b f32.
// ---------------------------------------------------------------------------
extern "C" void kernel_launch(void* const* d_in, const int* in_sizes, int n_in,
                              void* d_out, int out_size) {
    const int*   ids = (const int*)d_in[0];
    const float* W   = (const float*)d_in[1];
    const float* b   = (const float*)d_in[2];
    float*       out = (float*)d_out;

    dim3 tgrid(VOCAB / VT, EMBED / ET);   // 625 x 4
    transpose_W<<<tgrid, 256>>>((const float4*)W);

    gather_rows<<<ROWS / ROWS_PER_BLOCK, THREADS_B>>>(ids, b, out);
}